// round 1
// baseline (speedup 1.0000x reference)
#include <cuda_runtime.h>

#define NV 4096
#define NE 8192
#define FV 128
#define FE 64
#define FOUT 128

// Scratch (allocation-free rule: __device__ globals)
__device__ float g_d[NE];
__device__ float g_HW[NV * FOUT];
__device__ float g_M[(size_t)NV * NV];

// ---------------- kernel 1: d[e] = dot(H_e[e,:], p) ----------------
__global__ void k_edge_dot(const float* __restrict__ He, const float* __restrict__ p) {
    int row  = blockIdx.x * 8 + (threadIdx.x >> 5);
    int lane = threadIdx.x & 31;
    const float* r = He + (size_t)row * FE;
    float s = r[lane] * p[lane] + r[lane + 32] * p[lane + 32];
    #pragma unroll
    for (int o = 16; o; o >>= 1) s += __shfl_xor_sync(0xffffffffu, s, o);
    if (lane == 0) g_d[row] = s;
}

// ---------------- kernel 2: HW = H_v @ W  (16 rows / block) ----------------
__global__ void k_hw(const float* __restrict__ Hv, const float* __restrict__ W) {
    __shared__ float sh[16][FV];
    int r0  = blockIdx.x * 16;
    int tid = threadIdx.x;  // 128 threads
    #pragma unroll
    for (int l = 0; l < 4; l++) {
        int idx = tid + l * 128;      // float4 index, 512 total
        int r = idx >> 5;
        int c = (idx & 31) * 4;
        *(float4*)&sh[r][c] = *(const float4*)&Hv[(size_t)(r0 + r) * FV + c];
    }
    __syncthreads();
    int c = tid;
    float acc[16];
    #pragma unroll
    for (int r = 0; r < 16; r++) acc[r] = 0.f;
    for (int k = 0; k < FV; k++) {
        float w = W[k * FOUT + c];
        #pragma unroll
        for (int r = 0; r < 16; r++) acc[r] += sh[r][k] * w;
    }
    #pragma unroll
    for (int r = 0; r < 16; r++) g_HW[(size_t)(r0 + r) * FOUT + c] = acc[r];
}

// ---------------- kernel 3: M = (T*d) @ T^T  (symmetric, lower triangle) ----
#define SSTR 132   // padded smem stride (floats), keeps float4 alignment
__global__ void __launch_bounds__(256) k_mult(const float* __restrict__ T) {
    int bj = blockIdx.x, bi = blockIdx.y;
    if (bj > bi) return;

    __shared__ float As[16][SSTR];
    __shared__ float Bs[16][SSTR];
    __shared__ float sd[16];

    int tid = threadIdx.x;           // 256
    int tx  = tid & 15;              // 16 cols of threads
    int ty  = tid >> 4;              // 16 rows of threads

    float acc[8][8];
    #pragma unroll
    for (int i = 0; i < 8; i++)
        #pragma unroll
        for (int j = 0; j < 8; j++) acc[i][j] = 0.f;

    const float* Abase = T + (size_t)(bi * 128) * NE;
    const float* Bbase = T + (size_t)(bj * 128) * NE;

    for (int k0 = 0; k0 < NE; k0 += 16) {
        if (tid < 16) sd[tid] = g_d[k0 + tid];
        __syncthreads();  // sd ready; previous compute done

        #pragma unroll
        for (int l = 0; l < 2; l++) {
            int idx = tid + l * 256;       // 0..511 float4 slots
            int r   = idx >> 2;            // tile row 0..127
            int c4  = (idx & 3) * 4;       // k offset within tile
            float4 va = *(const float4*)(Abase + (size_t)r * NE + k0 + c4);
            float4 vb = *(const float4*)(Bbase + (size_t)r * NE + k0 + c4);
            As[c4 + 0][r] = va.x * sd[c4 + 0];
            As[c4 + 1][r] = va.y * sd[c4 + 1];
            As[c4 + 2][r] = va.z * sd[c4 + 2];
            As[c4 + 3][r] = va.w * sd[c4 + 3];
            Bs[c4 + 0][r] = vb.x;
            Bs[c4 + 1][r] = vb.y;
            Bs[c4 + 2][r] = vb.z;
            Bs[c4 + 3][r] = vb.w;
        }
        __syncthreads();

        #pragma unroll
        for (int kk = 0; kk < 16; kk++) {
            float4 a0 = *(const float4*)&As[kk][ty * 4];
            float4 a1 = *(const float4*)&As[kk][64 + ty * 4];
            float4 b0 = *(const float4*)&Bs[kk][tx * 4];
            float4 b1 = *(const float4*)&Bs[kk][64 + tx * 4];
            float ra[8] = {a0.x, a0.y, a0.z, a0.w, a1.x, a1.y, a1.z, a1.w};
            float rb[8] = {b0.x, b0.y, b0.z, b0.w, b1.x, b1.y, b1.z, b1.w};
            #pragma unroll
            for (int i = 0; i < 8; i++)
                #pragma unroll
                for (int j = 0; j < 8; j++)
                    acc[i][j] += ra[i] * rb[j];
        }
        __syncthreads();
    }

    // ---- writeback (primary tile, coalesced float4) ----
    #pragma unroll
    for (int i = 0; i < 8; i++) {
        int ri = (i < 4) ? (ty * 4 + i) : (64 + ty * 4 + i - 4);
        size_t gi = (size_t)(bi * 128 + ri);
        float4 v0 = make_float4(acc[i][0], acc[i][1], acc[i][2], acc[i][3]);
        float4 v1 = make_float4(acc[i][4], acc[i][5], acc[i][6], acc[i][7]);
        *(float4*)&g_M[gi * NV + bj * 128 + tx * 4]      = v0;
        *(float4*)&g_M[gi * NV + bj * 128 + 64 + tx * 4] = v1;
    }
    // ---- mirror tile (bi != bj): M[j,i] = M[i,j] ----
    if (bi != bj) {
        #pragma unroll
        for (int j = 0; j < 8; j++) {
            int cj = (j < 4) ? (tx * 4 + j) : (64 + tx * 4 + j - 4);
            size_t gj = (size_t)(bj * 128 + cj);
            float4 w0 = make_float4(acc[0][j], acc[1][j], acc[2][j], acc[3][j]);
            float4 w1 = make_float4(acc[4][j], acc[5][j], acc[6][j], acc[7][j]);
            *(float4*)&g_M[gj * NV + bi * 128 + ty * 4]      = w0;
            *(float4*)&g_M[gj * NV + bi * 128 + 64 + ty * 4] = w1;
        }
    }
}

// ---------------- kernel 4: out = (mask(M) * adj_v) @ HW + bias -------------
__global__ void __launch_bounds__(256) k_out(const float* __restrict__ adj_v,
                                             const float* __restrict__ bias,
                                             float* __restrict__ out) {
    __shared__ float As[16][68];    // [k][row], 64 rows
    __shared__ float Bs[16][SSTR];  // [k][col], 128 cols

    int bi  = blockIdx.x;           // 64 blocks of 64 rows
    int tid = threadIdx.x;          // 256
    int tx  = tid & 31;             // 32 col-threads * 4 cols
    int ty  = tid >> 5;             // 8 row-threads * 8 rows

    float acc[8][4];
    #pragma unroll
    for (int i = 0; i < 8; i++)
        #pragma unroll
        for (int j = 0; j < 4; j++) acc[i][j] = 0.f;

    for (int j0 = 0; j0 < NV; j0 += 16) {
        __syncthreads();
        {   // A' tile: 64 rows x 16 k, on-the-fly masked product
            int r  = tid >> 2;
            int c4 = (tid & 3) * 4;
            int gi = bi * 64 + r;
            size_t base = (size_t)gi * NV + j0 + c4;
            float4 av = *(const float4*)(adj_v + base);
            float4 mv = *(const float4*)(g_M + base);
            As[c4 + 0][r] = av.x * ((gi == j0 + c4 + 0) ? 1.f : mv.x);
            As[c4 + 1][r] = av.y * ((gi == j0 + c4 + 1) ? 1.f : mv.y);
            As[c4 + 2][r] = av.z * ((gi == j0 + c4 + 2) ? 1.f : mv.z);
            As[c4 + 3][r] = av.w * ((gi == j0 + c4 + 3) ? 1.f : mv.w);
        }
        #pragma unroll
        for (int l = 0; l < 2; l++) {  // HW tile: 16 rows x 128 cols
            int idx = tid + l * 256;
            int r = idx >> 5;
            int c = (idx & 31) * 4;
            *(float4*)&Bs[r][c] = *(const float4*)&g_HW[(size_t)(j0 + r) * FOUT + c];
        }
        __syncthreads();

        #pragma unroll
        for (int kk = 0; kk < 16; kk++) {
            float4 b = *(const float4*)&Bs[kk][tx * 4];
            #pragma unroll
            for (int i = 0; i < 8; i++) {
                float a = As[kk][ty * 8 + i];
                acc[i][0] += a * b.x;
                acc[i][1] += a * b.y;
                acc[i][2] += a * b.z;
                acc[i][3] += a * b.w;
            }
        }
    }

    float4 bv = *(const float4*)&bias[tx * 4];
    #pragma unroll
    for (int i = 0; i < 8; i++) {
        size_t gi = (size_t)(bi * 64 + ty * 8 + i);
        float4 v = make_float4(acc[i][0] + bv.x, acc[i][1] + bv.y,
                               acc[i][2] + bv.z, acc[i][3] + bv.w);
        *(float4*)&out[gi * FOUT + tx * 4] = v;
    }
}

// ---------------- launch ----------------
extern "C" void kernel_launch(void* const* d_in, const int* in_sizes, int n_in,
                              void* d_out, int out_size) {
    const float* Hv    = (const float*)d_in[0];
    const float* He    = (const float*)d_in[1];
    // d_in[2] = adj_e: unused by the node_layer path
    const float* adj_v = (const float*)d_in[3];
    const float* T     = (const float*)d_in[4];
    const float* W     = (const float*)d_in[5];
    const float* p     = (const float*)d_in[6];
    const float* bias  = (const float*)d_in[7];
    float* out = (float*)d_out;

    k_edge_dot<<<NE / 8, 256>>>(He, p);
    k_hw<<<NV / 16, 128>>>(Hv, W);
    dim3 g(32, 32);
    k_mult<<<g, 256>>>(T);
    k_out<<<NV / 64, 256>>>(adj_v, bias, out);

    // second output of the tuple: H_e passthrough
    if (out_size >= NV * FOUT + NE * FE) {
        cudaMemcpyAsync(out + NV * FOUT, He, (size_t)NE * FE * sizeof(float),
                        cudaMemcpyDeviceToDevice);
    }
}

// round 2
// speedup vs baseline: 1.1247x; 1.1247x over previous
#include <cuda_runtime.h>

#define NV 4096
#define NE 8192
#define FV 128
#define FE 64
#define FOUT 128

// Scratch (allocation-free rule: __device__ globals)
__device__ float g_d[NE];
__device__ float g_HW[NV * FOUT];
__device__ float g_M[(size_t)NV * NV];

// ---------------- packed f32x2 helpers (sm_103a FFMA2) ----------------
__device__ __forceinline__ void ffma2(unsigned long long& d,
                                      unsigned long long a,
                                      unsigned long long b) {
    asm("fma.rn.f32x2 %0, %1, %2, %0;" : "+l"(d) : "l"(a), "l"(b));
}
__device__ __forceinline__ unsigned long long dup2(float x) {
    unsigned long long r;
    asm("mov.b64 %0, {%1, %1};" : "=l"(r) : "f"(x));
    return r;
}
__device__ __forceinline__ float2 unpack2(unsigned long long v) {
    float2 f;
    asm("mov.b64 {%0, %1}, %2;" : "=f"(f.x), "=f"(f.y) : "l"(v));
    return f;
}

// ---------------- kernel 1: d[e] = dot(H_e[e,:], p) ----------------
__global__ void k_edge_dot(const float* __restrict__ He, const float* __restrict__ p) {
    int row  = blockIdx.x * 8 + (threadIdx.x >> 5);
    int lane = threadIdx.x & 31;
    const float* r = He + (size_t)row * FE;
    float s = r[lane] * p[lane] + r[lane + 32] * p[lane + 32];
    #pragma unroll
    for (int o = 16; o; o >>= 1) s += __shfl_xor_sync(0xffffffffu, s, o);
    if (lane == 0) g_d[row] = s;
}

// ---------------- kernel 2: HW = H_v @ W  (16 rows / block) ----------------
__global__ void k_hw(const float* __restrict__ Hv, const float* __restrict__ W) {
    __shared__ float sh[16][FV];
    int r0  = blockIdx.x * 16;
    int tid = threadIdx.x;  // 128 threads
    #pragma unroll
    for (int l = 0; l < 4; l++) {
        int idx = tid + l * 128;
        int r = idx >> 5;
        int c = (idx & 31) * 4;
        *(float4*)&sh[r][c] = *(const float4*)&Hv[(size_t)(r0 + r) * FV + c];
    }
    __syncthreads();
    int c = tid;
    float acc[16];
    #pragma unroll
    for (int r = 0; r < 16; r++) acc[r] = 0.f;
    for (int k = 0; k < FV; k++) {
        float w = W[k * FOUT + c];
        #pragma unroll
        for (int r = 0; r < 16; r++) acc[r] += sh[r][k] * w;
    }
    #pragma unroll
    for (int r = 0; r < 16; r++) g_HW[(size_t)(r0 + r) * FOUT + c] = acc[r];
}

// ---------------- kernel 3: M = (T*d) @ T^T  (symmetric, FFMA2 core) -------
#define SSTR 132   // padded smem stride (floats); 132*4=528 B, 16B-aligned rows
__global__ void __launch_bounds__(256) k_mult(const float* __restrict__ T) {
    int bj = blockIdx.x, bi = blockIdx.y;
    if (bj > bi) return;

    __shared__ float As[16][SSTR];
    __shared__ float Bs[16][SSTR];

    int tid = threadIdx.x;           // 256
    int tx  = tid & 15;              // 16 col-thread groups
    int ty  = tid >> 4;              // 16 row-thread groups

    // acc2[i][j] holds output columns (2j, 2j+1) of microtile row i
    unsigned long long acc2[8][4];
    #pragma unroll
    for (int i = 0; i < 8; i++)
        #pragma unroll
        for (int j = 0; j < 4; j++) acc2[i][j] = 0ull;

    const float* Abase = T + (size_t)(bi * 128) * NE;
    const float* Bbase = T + (size_t)(bj * 128) * NE;

    for (int k0 = 0; k0 < NE; k0 += 16) {
        #pragma unroll
        for (int l = 0; l < 2; l++) {
            int idx = tid + l * 256;       // 0..511 float4 slots
            int r   = idx >> 2;            // tile row 0..127
            int c4  = (idx & 3) * 4;       // k offset within tile
            float4 va = *(const float4*)(Abase + (size_t)r * NE + k0 + c4);
            float4 vb = *(const float4*)(Bbase + (size_t)r * NE + k0 + c4);
            float4 dv = *(const float4*)(g_d + k0 + c4);
            As[c4 + 0][r] = va.x * dv.x;
            As[c4 + 1][r] = va.y * dv.y;
            As[c4 + 2][r] = va.z * dv.z;
            As[c4 + 3][r] = va.w * dv.w;
            Bs[c4 + 0][r] = vb.x;
            Bs[c4 + 1][r] = vb.y;
            Bs[c4 + 2][r] = vb.z;
            Bs[c4 + 3][r] = vb.w;
        }
        __syncthreads();

        #pragma unroll
        for (int kk = 0; kk < 16; kk++) {
            float4 a0 = *(const float4*)&As[kk][ty * 4];
            float4 a1 = *(const float4*)&As[kk][64 + ty * 4];
            ulonglong2 b0 = *(const ulonglong2*)&Bs[kk][tx * 4];
            ulonglong2 b1 = *(const ulonglong2*)&Bs[kk][64 + tx * 4];
            unsigned long long av[8];
            av[0] = dup2(a0.x); av[1] = dup2(a0.y);
            av[2] = dup2(a0.z); av[3] = dup2(a0.w);
            av[4] = dup2(a1.x); av[5] = dup2(a1.y);
            av[6] = dup2(a1.z); av[7] = dup2(a1.w);
            unsigned long long bv[4] = {b0.x, b0.y, b1.x, b1.y};
            #pragma unroll
            for (int i = 0; i < 8; i++)
                #pragma unroll
                for (int j = 0; j < 4; j++)
                    ffma2(acc2[i][j], av[i], bv[j]);
        }
        __syncthreads();
    }

    // unpack to scalar view
    float accf[8][8];
    #pragma unroll
    for (int i = 0; i < 8; i++)
        #pragma unroll
        for (int j = 0; j < 4; j++) {
            float2 f = unpack2(acc2[i][j]);
            accf[i][2 * j]     = f.x;
            accf[i][2 * j + 1] = f.y;
        }

    // ---- writeback (primary tile, coalesced float4) ----
    #pragma unroll
    for (int i = 0; i < 8; i++) {
        int ri = (i < 4) ? (ty * 4 + i) : (64 + ty * 4 + i - 4);
        size_t gi = (size_t)(bi * 128 + ri);
        float4 v0 = make_float4(accf[i][0], accf[i][1], accf[i][2], accf[i][3]);
        float4 v1 = make_float4(accf[i][4], accf[i][5], accf[i][6], accf[i][7]);
        *(float4*)&g_M[gi * NV + bj * 128 + tx * 4]      = v0;
        *(float4*)&g_M[gi * NV + bj * 128 + 64 + tx * 4] = v1;
    }
    // ---- mirror tile (bi != bj): M[j,i] = M[i,j] ----
    if (bi != bj) {
        #pragma unroll
        for (int j = 0; j < 8; j++) {
            int cj = (j < 4) ? (tx * 4 + j) : (64 + tx * 4 + j - 4);
            size_t gj = (size_t)(bj * 128 + cj);
            float4 w0 = make_float4(accf[0][j], accf[1][j], accf[2][j], accf[3][j]);
            float4 w1 = make_float4(accf[4][j], accf[5][j], accf[6][j], accf[7][j]);
            *(float4*)&g_M[gj * NV + bi * 128 + ty * 4]      = w0;
            *(float4*)&g_M[gj * NV + bi * 128 + 64 + ty * 4] = w1;
        }
    }
}

// ---------------- kernel 4: out = (mask(M) * adj_v) @ HW + bias -------------
// 128 CTAs of 32 rows (full-chip coverage), k-chunk 32.
__global__ void __launch_bounds__(256) k_out(const float* __restrict__ adj_v,
                                             const float* __restrict__ bias,
                                             float* __restrict__ out) {
    __shared__ float As[32][36];    // [k][row], 32 rows
    __shared__ float Bs[32][SSTR];  // [k][col], 128 cols

    int bi  = blockIdx.x;           // 128 blocks of 32 rows
    int tid = threadIdx.x;          // 256
    int tx  = tid & 31;             // 32 col-threads * 4 cols = 128
    int ty  = tid >> 5;             // 8 row-threads * 4 rows  = 32

    float acc[4][4];
    #pragma unroll
    for (int i = 0; i < 4; i++)
        #pragma unroll
        for (int j = 0; j < 4; j++) acc[i][j] = 0.f;

    for (int j0 = 0; j0 < NV; j0 += 32) {
        __syncthreads();
        {   // A' tile: 32 rows x 32 k, on-the-fly masked product (1 float4/thr)
            int r  = tid >> 3;           // 0..31
            int c4 = (tid & 7) * 4;      // 0..28
            int gi = bi * 32 + r;
            size_t base = (size_t)gi * NV + j0 + c4;
            float4 av = *(const float4*)(adj_v + base);
            float4 mv = *(const float4*)(g_M + base);
            As[c4 + 0][r] = av.x * ((gi == j0 + c4 + 0) ? 1.f : mv.x);
            As[c4 + 1][r] = av.y * ((gi == j0 + c4 + 1) ? 1.f : mv.y);
            As[c4 + 2][r] = av.z * ((gi == j0 + c4 + 2) ? 1.f : mv.z);
            As[c4 + 3][r] = av.w * ((gi == j0 + c4 + 3) ? 1.f : mv.w);
        }
        #pragma unroll
        for (int l = 0; l < 4; l++) {  // HW tile: 32 rows x 128 cols
            int idx = tid + l * 256;
            int r = idx >> 5;
            int c = (idx & 31) * 4;
            *(float4*)&Bs[r][c] = *(const float4*)&g_HW[(size_t)(j0 + r) * FOUT + c];
        }
        __syncthreads();

        #pragma unroll
        for (int kk = 0; kk < 32; kk++) {
            float4 b = *(const float4*)&Bs[kk][tx * 4];
            #pragma unroll
            for (int i = 0; i < 4; i++) {
                float a = As[kk][ty * 4 + i];
                acc[i][0] += a * b.x;
                acc[i][1] += a * b.y;
                acc[i][2] += a * b.z;
                acc[i][3] += a * b.w;
            }
        }
    }

    float4 bv = *(const float4*)&bias[tx * 4];
    #pragma unroll
    for (int i = 0; i < 4; i++) {
        size_t gi = (size_t)(bi * 32 + ty * 4 + i);
        float4 v = make_float4(acc[i][0] + bv.x, acc[i][1] + bv.y,
                               acc[i][2] + bv.z, acc[i][3] + bv.w);
        *(float4*)&out[gi * FOUT + tx * 4] = v;
    }
}

// ---------------- launch ----------------
extern "C" void kernel_launch(void* const* d_in, const int* in_sizes, int n_in,
                              void* d_out, int out_size) {
    const float* Hv    = (const float*)d_in[0];
    const float* He    = (const float*)d_in[1];
    // d_in[2] = adj_e: unused by the node_layer path
    const float* adj_v = (const float*)d_in[3];
    const float* T     = (const float*)d_in[4];
    const float* W     = (const float*)d_in[5];
    const float* p     = (const float*)d_in[6];
    const float* bias  = (const float*)d_in[7];
    float* out = (float*)d_out;

    k_edge_dot<<<NE / 8, 256>>>(He, p);
    k_hw<<<NV / 16, 128>>>(Hv, W);
    dim3 g(32, 32);
    k_mult<<<g, 256>>>(T);
    k_out<<<NV / 32, 256>>>(adj_v, bias, out);

    // second output of the tuple: H_e passthrough
    if (out_size >= NV * FOUT + NE * FE) {
        cudaMemcpyAsync(out + NV * FOUT, He, (size_t)NE * FE * sizeof(float),
                        cudaMemcpyDeviceToDevice);
    }
}

// round 4
// speedup vs baseline: 2.2716x; 2.0198x over previous
#include <cuda_runtime.h>
#include <cuda_bf16.h>
#include <cstdint>

#define NV 4096
#define NE 8192
#define FV 128
#define FE 64
#define FOUT 128

// Scratch (allocation-free rule: __device__ globals)
__device__ float g_d[NE];
__device__ float g_HW[NV * FOUT];
__device__ float g_M[(size_t)NV * NV];
// bf16 split copies of T: A = T*d (row i, col k scaled by d[k]), B = T
__device__ __nv_bfloat16 g_Ah[(size_t)NV * NE];
__device__ __nv_bfloat16 g_Al[(size_t)NV * NE];
__device__ __nv_bfloat16 g_Bh[(size_t)NV * NE];
__device__ __nv_bfloat16 g_Bl[(size_t)NV * NE];

// ======================= helpers =======================
__device__ __forceinline__ uint32_t smem_u32(const void* p) {
    uint32_t a;
    asm("{ .reg .u64 t; cvta.to.shared.u64 t, %1; cvt.u32.u64 %0, t; }" : "=r"(a) : "l"(p));
    return a;
}
// split (x,y) into packed bf16x2 hi + bf16x2 lo residual
__device__ __forceinline__ void split2(float x, float y, uint32_t& hi, uint32_t& lo) {
    __nv_bfloat162 h = __floats2bfloat162_rn(x, y);
    uint32_t hb = *(uint32_t*)&h;
    float hx = __uint_as_float(hb << 16);
    float hy = __uint_as_float(hb & 0xFFFF0000u);
    __nv_bfloat162 l = __floats2bfloat162_rn(x - hx, y - hy);
    hi = hb;
    lo = *(uint32_t*)&l;
}
__device__ __forceinline__ void mma16816(float* c, const uint32_t* a, const uint32_t* b) {
    asm volatile(
        "mma.sync.aligned.m16n8k16.row.col.f32.bf16.bf16.f32 "
        "{%0,%1,%2,%3}, {%4,%5,%6,%7}, {%8,%9}, {%0,%1,%2,%3};"
        : "+f"(c[0]), "+f"(c[1]), "+f"(c[2]), "+f"(c[3])
        : "r"(a[0]), "r"(a[1]), "r"(a[2]), "r"(a[3]), "r"(b[0]), "r"(b[1]));
}
__device__ __forceinline__ void ldsm_x4(uint32_t* r, uint32_t addr) {
    asm volatile("ldmatrix.sync.aligned.m8n8.x4.shared.b16 {%0,%1,%2,%3}, [%4];"
                 : "=r"(r[0]), "=r"(r[1]), "=r"(r[2]), "=r"(r[3]) : "r"(addr));
}
__device__ __forceinline__ void ldsm_x2(uint32_t* r, uint32_t addr) {
    asm volatile("ldmatrix.sync.aligned.m8n8.x2.shared.b16 {%0,%1}, [%2];"
                 : "=r"(r[0]), "=r"(r[1]) : "r"(addr));
}
__device__ __forceinline__ void cp16(uint32_t saddr, const void* gaddr) {
    asm volatile("cp.async.ca.shared.global [%0], [%1], 16;" :: "r"(saddr), "l"(gaddr));
}

// ---------------- kernel 1: d[e] = dot(H_e[e,:], p) ----------------
__global__ void k_edge_dot(const float* __restrict__ He, const float* __restrict__ p) {
    int row  = blockIdx.x * 8 + (threadIdx.x >> 5);
    int lane = threadIdx.x & 31;
    const float* r = He + (size_t)row * FE;
    float s = r[lane] * p[lane] + r[lane + 32] * p[lane + 32];
    #pragma unroll
    for (int o = 16; o; o >>= 1) s += __shfl_xor_sync(0xffffffffu, s, o);
    if (lane == 0) g_d[row] = s;
}

// ---------------- kernel 1b: bf16 split precompute ----------------
// thread -> 8 consecutive elements of one row of T
__global__ void __launch_bounds__(256) k_split(const float* __restrict__ T) {
    size_t idx = (size_t)blockIdx.x * 256 + threadIdx.x;
    int row = (int)(idx >> 10);          // NE/8 = 1024 slots per row
    int c0  = (int)(idx & 1023) * 8;
    const float* pt = T + (size_t)row * NE + c0;
    float4 t0 = *(const float4*)pt;
    float4 t1 = *(const float4*)(pt + 4);
    float4 d0 = *(const float4*)(g_d + c0);
    float4 d1 = *(const float4*)(g_d + c0 + 4);

    uint4 bh, bl, ah, al;
    split2(t0.x, t0.y, bh.x, bl.x);
    split2(t0.z, t0.w, bh.y, bl.y);
    split2(t1.x, t1.y, bh.z, bl.z);
    split2(t1.z, t1.w, bh.w, bl.w);
    split2(t0.x * d0.x, t0.y * d0.y, ah.x, al.x);
    split2(t0.z * d0.z, t0.w * d0.w, ah.y, al.y);
    split2(t1.x * d1.x, t1.y * d1.y, ah.z, al.z);
    split2(t1.z * d1.z, t1.w * d1.w, ah.w, al.w);

    size_t boff = ((size_t)row * NE + c0) * 2;  // byte offset
    *(uint4*)((char*)g_Ah + boff) = ah;
    *(uint4*)((char*)g_Al + boff) = al;
    *(uint4*)((char*)g_Bh + boff) = bh;
    *(uint4*)((char*)g_Bl + boff) = bl;
}

// ---------------- kernel 2: HW = H_v @ W  (16 rows / block) ----------------
__global__ void k_hw(const float* __restrict__ Hv, const float* __restrict__ W) {
    __shared__ float sh[16][FV];
    int r0  = blockIdx.x * 16;
    int tid = threadIdx.x;  // 128
    #pragma unroll
    for (int l = 0; l < 4; l++) {
        int idx = tid + l * 128;
        int r = idx >> 5;
        int c = (idx & 31) * 4;
        *(float4*)&sh[r][c] = *(const float4*)&Hv[(size_t)(r0 + r) * FV + c];
    }
    __syncthreads();
    int c = tid;
    float acc[16];
    #pragma unroll
    for (int r = 0; r < 16; r++) acc[r] = 0.f;
    for (int k = 0; k < FV; k++) {
        float w = W[k * FOUT + c];
        #pragma unroll
        for (int r = 0; r < 16; r++) acc[r] += sh[r][k] * w;
    }
    #pragma unroll
    for (int r = 0; r < 16; r++) g_HW[(size_t)(r0 + r) * FOUT + c] = acc[r];
}

// ---------------- kernel 3: M = (T*d) @ T^T via mma.sync bf16x3 ------------
// 128x128 tile per CTA, 8 warps (2x4) of 64x32, k-chunk 32.
#define ASTR 40   // bf16 per smem row (80 B): conflict-free ldmatrix, 16B-aligned
__global__ void __launch_bounds__(256, 2) k_mult_hmma() {
    int bj = blockIdx.x, bi = blockIdx.y;
    if (bj > bi) return;

    __shared__ __nv_bfloat16 sAh[128 * ASTR];
    __shared__ __nv_bfloat16 sAl[128 * ASTR];
    __shared__ __nv_bfloat16 sBh[128 * ASTR];
    __shared__ __nv_bfloat16 sBl[128 * ASTR];

    const int tid = threadIdx.x, lane = tid & 31, wid = tid >> 5;
    const int wr = wid >> 2, wc = wid & 3;   // warp 64-row band, 32-col band

    const uint32_t uAh = smem_u32(sAh), uAl = smem_u32(sAl);
    const uint32_t uBh = smem_u32(sBh), uBl = smem_u32(sBl);

    float acc[4][4][4];
    #pragma unroll
    for (int i = 0; i < 4; i++)
        #pragma unroll
        for (int j = 0; j < 4; j++)
            #pragma unroll
            for (int q = 0; q < 4; q++) acc[i][j][q] = 0.f;

    // cp.async slot mapping: slot s in [0,512): row = s>>2, k16off = (s&3)*8
    const int s0 = tid, s1 = tid + 256;
    const int r0s = s0 >> 2, k0s = (s0 & 3) * 8;
    const int r1s = s1 >> 2, k1s = (s1 & 3) * 8;
    const __nv_bfloat16* gA0h = g_Ah + (size_t)(bi * 128 + r0s) * NE + k0s;
    const __nv_bfloat16* gA1h = g_Ah + (size_t)(bi * 128 + r1s) * NE + k1s;
    const __nv_bfloat16* gA0l = g_Al + (size_t)(bi * 128 + r0s) * NE + k0s;
    const __nv_bfloat16* gA1l = g_Al + (size_t)(bi * 128 + r1s) * NE + k1s;
    const __nv_bfloat16* gB0h = g_Bh + (size_t)(bj * 128 + r0s) * NE + k0s;
    const __nv_bfloat16* gB1h = g_Bh + (size_t)(bj * 128 + r1s) * NE + k1s;
    const __nv_bfloat16* gB0l = g_Bl + (size_t)(bj * 128 + r0s) * NE + k0s;
    const __nv_bfloat16* gB1l = g_Bl + (size_t)(bj * 128 + r1s) * NE + k1s;
    const uint32_t sm0 = r0s * (ASTR * 2) + k0s * 2;
    const uint32_t sm1 = r1s * (ASTR * 2) + k1s * 2;

    // ldmatrix per-lane bases
    const int arow = wr * 64 + (lane & 15);
    const int akof = (lane >> 4) * 8;
    const int brow = wc * 32 + (lane & 7);
    const int bkof = ((lane >> 3) & 1) * 8;

    for (int k0 = 0; k0 < NE; k0 += 32) {
        __syncthreads();
        cp16(uAh + sm0, gA0h + k0);  cp16(uAh + sm1, gA1h + k0);
        cp16(uAl + sm0, gA0l + k0);  cp16(uAl + sm1, gA1l + k0);
        cp16(uBh + sm0, gB0h + k0);  cp16(uBh + sm1, gB1h + k0);
        cp16(uBl + sm0, gB0l + k0);  cp16(uBl + sm1, gB1l + k0);
        asm volatile("cp.async.commit_group;");
        asm volatile("cp.async.wait_group 0;" ::: "memory");
        __syncthreads();

        #pragma unroll
        for (int kk = 0; kk < 32; kk += 16) {
            uint32_t bh[4][2], bl[4][2];
            #pragma unroll
            for (int nt = 0; nt < 4; nt++) {
                uint32_t boff = (uint32_t)(brow + nt * 8) * (ASTR * 2) + (kk + bkof) * 2;
                ldsm_x2(bh[nt], uBh + boff);
                ldsm_x2(bl[nt], uBl + boff);
            }
            #pragma unroll
            for (int mt = 0; mt < 4; mt++) {
                uint32_t aoff = (uint32_t)(arow + mt * 16) * (ASTR * 2) + (kk + akof) * 2;
                uint32_t ah[4], al[4];
                ldsm_x4(ah, uAh + aoff);
                ldsm_x4(al, uAl + aoff);
                #pragma unroll
                for (int nt = 0; nt < 4; nt++) {
                    mma16816(acc[mt][nt], ah, bh[nt]);
                    mma16816(acc[mt][nt], ah, bl[nt]);
                    mma16816(acc[mt][nt], al, bh[nt]);
                }
            }
        }
    }

    // ---- writeback: primary (+ mirror when off-diagonal) ----
    const int g  = lane >> 2;
    const int cp = (lane & 3) * 2;
    #pragma unroll
    for (int mt = 0; mt < 4; mt++)
        #pragma unroll
        for (int nt = 0; nt < 4; nt++) {
            float* c = acc[mt][nt];
            int r = bi * 128 + wr * 64 + mt * 16 + g;
            int q = bj * 128 + wc * 32 + nt * 8 + cp;
            *(float2*)&g_M[(size_t)r * NV + q]       = make_float2(c[0], c[1]);
            *(float2*)&g_M[(size_t)(r + 8) * NV + q] = make_float2(c[2], c[3]);
            if (bi != bj) {
                g_M[(size_t)q * NV + r]           = c[0];
                g_M[(size_t)(q + 1) * NV + r]     = c[1];
                g_M[(size_t)q * NV + r + 8]       = c[2];
                g_M[(size_t)(q + 1) * NV + r + 8] = c[3];
            }
        }
}

// ---------------- kernel 4: out = (mask(M) * adj_v) @ HW + bias -------------
// 256 CTAs of 16 rows, k-chunk 32.
__global__ void __launch_bounds__(256) k_out(const float* __restrict__ adj_v,
                                             const float* __restrict__ bias,
                                             float* __restrict__ out) {
    __shared__ float As[32][20];    // [k][row], 16 rows (+pad)
    __shared__ float Bs[32][132];   // [k][col], 128 cols (+pad)

    int bi  = blockIdx.x;           // 256 blocks of 16 rows
    int tid = threadIdx.x;          // 256
    int tx  = tid & 31;             // col group * 4
    int ty  = tid >> 5;             // 8 groups * 2 rows

    float acc[2][4];
    #pragma unroll
    for (int i = 0; i < 2; i++)
        #pragma unroll
        for (int j = 0; j < 4; j++) acc[i][j] = 0.f;

    for (int j0 = 0; j0 < NV; j0 += 32) {
        __syncthreads();
        if (tid < 128) {    // A' tile: 16 rows x 32 k, masked product
            int r  = tid >> 3;
            int c4 = (tid & 7) * 4;
            int gi = bi * 16 + r;
            size_t base = (size_t)gi * NV + j0 + c4;
            float4 av = *(const float4*)(adj_v + base);
            float4 mv = *(const float4*)(g_M + base);
            As[c4 + 0][r] = av.x * ((gi == j0 + c4 + 0) ? 1.f : mv.x);
            As[c4 + 1][r] = av.y * ((gi == j0 + c4 + 1) ? 1.f : mv.y);
            As[c4 + 2][r] = av.z * ((gi == j0 + c4 + 2) ? 1.f : mv.z);
            As[c4 + 3][r] = av.w * ((gi == j0 + c4 + 3) ? 1.f : mv.w);
        }
        #pragma unroll
        for (int l = 0; l < 4; l++) {   // HW tile: 32 rows x 128 cols
            int idx = tid + l * 256;
            int r = idx >> 5;
            int c = (idx & 31) * 4;
            *(float4*)&Bs[r][c] = *(const float4*)&g_HW[(size_t)(j0 + r) * FOUT + c];
        }
        __syncthreads();

        #pragma unroll
        for (int kk = 0; kk < 32; kk++) {
            float4 b = *(const float4*)&Bs[kk][tx * 4];
            float a0 = As[kk][ty * 2 + 0];
            float a1 = As[kk][ty * 2 + 1];
            acc[0][0] += a0 * b.x; acc[0][1] += a0 * b.y;
            acc[0][2] += a0 * b.z; acc[0][3] += a0 * b.w;
            acc[1][0] += a1 * b.x; acc[1][1] += a1 * b.y;
            acc[1][2] += a1 * b.z; acc[1][3] += a1 * b.w;
        }
    }

    float4 bv = *(const float4*)&bias[tx * 4];
    #pragma unroll
    for (int i = 0; i < 2; i++) {
        size_t gi = (size_t)(bi * 16 + ty * 2 + i);
        float4 v = make_float4(acc[i][0] + bv.x, acc[i][1] + bv.y,
                               acc[i][2] + bv.z, acc[i][3] + bv.w);
        *(float4*)&out[gi * FOUT + tx * 4] = v;
    }
}

// ---------------- launch ----------------
extern "C" void kernel_launch(void* const* d_in, const int* in_sizes, int n_in,
                              void* d_out, int out_size) {
    const float* Hv    = (const float*)d_in[0];
    const float* He    = (const float*)d_in[1];
    // d_in[2] = adj_e: unused by the node_layer path
    const float* adj_v = (const float*)d_in[3];
    const float* T     = (const float*)d_in[4];
    const float* W     = (const float*)d_in[5];
    const float* p     = (const float*)d_in[6];
    const float* bias  = (const float*)d_in[7];
    float* out = (float*)d_out;

    k_edge_dot<<<NE / 8, 256>>>(He, p);
    k_split<<<(NV * (NE / 8)) / 256, 256>>>(T);
    k_hw<<<NV / 16, 128>>>(Hv, W);
    dim3 g(32, 32);
    k_mult_hmma<<<g, 256>>>();
    k_out<<<NV / 16, 256>>>(adj_v, bias, out);

    // second output of the tuple: H_e passthrough
    if (out_size >= NV * FOUT + NE * FE) {
        cudaMemcpyAsync(out + NV * FOUT, He, (size_t)NE * FE * sizeof(float),
                        cudaMemcpyDeviceToDevice);
    }
}